// round 2
// baseline (speedup 1.0000x reference)
#include <cuda_runtime.h>
#include <cuda_bf16.h>
#include <math.h>

// Shapes (fixed for this problem)
#define BB 4
#define NN 2048
#define DD 256
#define HH 8
#define dH 32
#define ROWS (BB*NN)            // 8192
#define SCALE 0.17677669529663687f   // 1/sqrt(32)

// -------------------- scratch (device globals; no allocation allowed) -----
__device__ float g_h  [ROWS*DD];        // LN output (reused for LN1 and LN2)
__device__ float g_qkv[ROWS*3*DD];      // qkv projection (rope applied in-place)
__device__ float g_att[ROWS*DD];        // attention output [B,N,H*d]
__device__ float g_x2 [ROWS*DD];        // x + proj residual
__device__ float g_mid[ROWS*2*DD];      // FFN hidden

// -------------------- LayerNorm: one block per row ------------------------
__global__ void __launch_bounds__(256) ln_kernel(
    const float* __restrict__ x, const float* __restrict__ g,
    const float* __restrict__ b, float* __restrict__ y)
{
    int row = blockIdx.x;
    int t = threadIdx.x;
    float v = x[(long)row*DD + t];
    float s = v, s2 = v*v;
    #pragma unroll
    for (int o = 16; o; o >>= 1) {
        s  += __shfl_xor_sync(0xffffffffu, s,  o);
        s2 += __shfl_xor_sync(0xffffffffu, s2, o);
    }
    __shared__ float ws[8], ws2[8];
    int w = t >> 5, l = t & 31;
    if (l == 0) { ws[w] = s; ws2[w] = s2; }
    __syncthreads();
    s = 0.f; s2 = 0.f;
    #pragma unroll
    for (int i = 0; i < 8; i++) { s += ws[i]; s2 += ws2[i]; }
    float mu  = s * (1.f/DD);
    float var = s2 * (1.f/DD) - mu*mu;
    float inv = rsqrtf(var + 1e-5f);
    y[(long)row*DD + t] = (v - mu) * inv * g[t] + b[t];
}

// -------------------- fp32 GEMM: C = A@B (+bias)(+relu)(+res) -------------
// A: [M,K] rm, B: [K,Nn] rm, BM=BN=128, BK=16, 256 threads, 8x8 micro-tile.
__global__ void __launch_bounds__(256) gemm_kernel(
    const float* __restrict__ A, const float* __restrict__ B,
    const float* __restrict__ bias, const float* __restrict__ Res,
    float* __restrict__ C, int M, int Nn, int K, int relu)
{
    __shared__ float As[16][128];
    __shared__ float Bs[16][128];

    int tid = threadIdx.x;
    int tx = tid & 15, ty = tid >> 4;
    int m0 = blockIdx.y * 128, n0 = blockIdx.x * 128;

    float acc[8][8];
    #pragma unroll
    for (int i = 0; i < 8; i++)
        #pragma unroll
        for (int j = 0; j < 8; j++) acc[i][j] = 0.f;

    for (int kt = 0; kt < K; kt += 16) {
        #pragma unroll
        for (int l = 0; l < 2; l++) {
            int idx = l*256 + tid;
            // A tile: 128 rows x 16 cols = 512 float4 loads (2 per thread)
            int r = idx >> 2, c4 = (idx & 3) << 2;
            float4 a = *(const float4*)(A + (long)(m0 + r)*K + kt + c4);
            As[c4+0][r] = a.x; As[c4+1][r] = a.y;
            As[c4+2][r] = a.z; As[c4+3][r] = a.w;
            // B tile: 16 rows x 128 cols
            int br = idx >> 5, bc = (idx & 31) << 2;
            *(float4*)&Bs[br][bc] = *(const float4*)(B + (long)(kt + br)*Nn + n0 + bc);
        }
        __syncthreads();
        #pragma unroll
        for (int k = 0; k < 16; k++) {
            float af[8], bf[8];
            *(float4*)(af)   = *(float4*)&As[k][ty*8];
            *(float4*)(af+4) = *(float4*)&As[k][ty*8+4];
            *(float4*)(bf)   = *(float4*)&Bs[k][tx*8];
            *(float4*)(bf+4) = *(float4*)&Bs[k][tx*8+4];
            #pragma unroll
            for (int i = 0; i < 8; i++)
                #pragma unroll
                for (int j = 0; j < 8; j++)
                    acc[i][j] = fmaf(af[i], bf[j], acc[i][j]);
        }
        __syncthreads();
    }

    float bv[8];
    *(float4*)(bv)   = *(const float4*)(bias + n0 + tx*8);
    *(float4*)(bv+4) = *(const float4*)(bias + n0 + tx*8 + 4);

    #pragma unroll
    for (int i = 0; i < 8; i++) {
        long row = m0 + ty*8 + i;
        float* cp = C + row*Nn + n0 + tx*8;
        float v[8];
        #pragma unroll
        for (int j = 0; j < 8; j++) {
            v[j] = acc[i][j] + bv[j];
            if (relu) v[j] = fmaxf(v[j], 0.f);
        }
        if (Res) {
            const float* rp = Res + row*Nn + n0 + tx*8;
            float4 r0 = *(const float4*)rp, r1 = *(const float4*)(rp+4);
            v[0]+=r0.x; v[1]+=r0.y; v[2]+=r0.z; v[3]+=r0.w;
            v[4]+=r1.x; v[5]+=r1.y; v[6]+=r1.z; v[7]+=r1.w;
        }
        *(float4*)(cp)   = make_float4(v[0],v[1],v[2],v[3]);
        *(float4*)(cp+4) = make_float4(v[4],v[5],v[6],v[7]);
    }
}

// -------------------- RoPE in-place on q,k parts of qkv -------------------
// qkv layout: row (b*N+n), col = t*256 + h*32 + dd   (t=0:q, 1:k, 2:v)
__global__ void __launch_bounds__(256) rope_kernel(
    float* __restrict__ qkv, const float* __restrict__ cosb,
    const float* __restrict__ sinb)
{
    int gid = blockIdx.x * 256 + threadIdx.x;   // [0, B*N*2*H*16)
    int i = gid & 15;
    int h = (gid >> 4) & 7;
    int t = (gid >> 7) & 1;
    int n = (gid >> 8) & 2047;
    int b = gid >> 19;
    float c = cosb[n*16 + i], s = sinb[n*16 + i];
    long base = ((long)(b*NN + n))*(3*DD) + t*DD + h*dH + 2*i;
    float e = qkv[base], o = qkv[base+1];
    qkv[base]   = e*c - o*s;
    qkv[base+1] = e*s + o*c;
}

// -------------------- Flash attention: 1 thread = 1 query row -------------
__global__ void __launch_bounds__(128) attn_kernel(
    const float* __restrict__ qkv, float* __restrict__ out)
{
    int b = blockIdx.z, h = blockIdx.y;
    int tid = threadIdx.x;
    int qrow = blockIdx.x * 128 + tid;

    const float* qp = qkv + ((long)(b*NN + qrow))*(3*DD) + h*dH;
    float q[32];
    #pragma unroll
    for (int i = 0; i < 8; i++) {
        float4 t4 = *(const float4*)(qp + i*4);
        q[i*4+0] = t4.x*SCALE; q[i*4+1] = t4.y*SCALE;
        q[i*4+2] = t4.z*SCALE; q[i*4+3] = t4.w*SCALE;
    }
    float o[32];
    #pragma unroll
    for (int i = 0; i < 32; i++) o[i] = 0.f;
    float m = -1e30f, s = 0.f;

    __shared__ float ks[32][32];
    __shared__ float vs[32][32];

    const float* kbase = qkv + (long)b*NN*(3*DD) + DD   + h*dH;
    const float* vbase = qkv + (long)b*NN*(3*DD) + 2*DD + h*dH;

    for (int jt = 0; jt < NN/32; jt++) {
        __syncthreads();
        // 32 keys x 32 floats = 256 float4 loads for K, same for V.
        // 128 threads x 2 iters: key = idx>>3 (8 float4 per key), c4 = (idx&7)*4
        #pragma unroll
        for (int l = 0; l < 2; l++) {
            int idx = l*128 + tid;
            int key = idx >> 3, c4 = (idx & 7) << 2;
            long off = (long)(jt*32 + key)*(3*DD) + c4;
            *(float4*)&ks[key][c4] = *(const float4*)(kbase + off);
            *(float4*)&vs[key][c4] = *(const float4*)(vbase + off);
        }
        __syncthreads();

        float sc[32];
        float tmax = -1e30f;
        #pragma unroll
        for (int j = 0; j < 32; j++) {
            float a0=0.f, a1=0.f, a2=0.f, a3=0.f;
            #pragma unroll
            for (int dd = 0; dd < 8; dd++) {
                float4 kv = *(const float4*)&ks[j][dd*4];
                a0 = fmaf(q[dd*4+0], kv.x, a0);
                a1 = fmaf(q[dd*4+1], kv.y, a1);
                a2 = fmaf(q[dd*4+2], kv.z, a2);
                a3 = fmaf(q[dd*4+3], kv.w, a3);
            }
            float v = (a0+a1) + (a2+a3);
            sc[j] = v;
            tmax = fmaxf(tmax, v);
        }
        float nm = fmaxf(m, tmax);
        float corr = __expf(m - nm);
        s *= corr;
        #pragma unroll
        for (int i = 0; i < 32; i++) o[i] *= corr;
        #pragma unroll
        for (int j = 0; j < 32; j++) {
            float p = __expf(sc[j] - nm);
            s += p;
            #pragma unroll
            for (int dd = 0; dd < 8; dd++) {
                float4 vv = *(const float4*)&vs[j][dd*4];
                o[dd*4+0] = fmaf(p, vv.x, o[dd*4+0]);
                o[dd*4+1] = fmaf(p, vv.y, o[dd*4+1]);
                o[dd*4+2] = fmaf(p, vv.z, o[dd*4+2]);
                o[dd*4+3] = fmaf(p, vv.w, o[dd*4+3]);
            }
        }
        m = nm;
    }

    float inv = 1.f / s;
    float* op = out + ((long)(b*NN + qrow))*DD + h*dH;
    #pragma unroll
    for (int i = 0; i < 8; i++) {
        float4 t4;
        t4.x = o[i*4+0]*inv; t4.y = o[i*4+1]*inv;
        t4.z = o[i*4+2]*inv; t4.w = o[i*4+3]*inv;
        *(float4*)(op + i*4) = t4;
    }
}

// -------------------- launch ----------------------------------------------
extern "C" void kernel_launch(void* const* d_in, const int* in_sizes, int n_in,
                              void* d_out, int out_size)
{
    const float* x      = (const float*)d_in[0];
    const float* cosb   = (const float*)d_in[1];
    const float* sinb   = (const float*)d_in[2];
    const float* w_qkv  = (const float*)d_in[3];
    const float* b_qkv  = (const float*)d_in[4];
    const float* w_proj = (const float*)d_in[5];
    const float* b_proj = (const float*)d_in[6];
    const float* ln1_g  = (const float*)d_in[7];
    const float* ln1_b  = (const float*)d_in[8];
    const float* ln2_g  = (const float*)d_in[9];
    const float* ln2_b  = (const float*)d_in[10];
    const float* w1     = (const float*)d_in[11];
    const float* b1     = (const float*)d_in[12];
    const float* w2     = (const float*)d_in[13];
    const float* b2     = (const float*)d_in[14];
    float* out = (float*)d_out;

    float *sp_h, *sp_qkv, *sp_att, *sp_x2, *sp_mid;
    cudaGetSymbolAddress((void**)&sp_h,   g_h);
    cudaGetSymbolAddress((void**)&sp_qkv, g_qkv);
    cudaGetSymbolAddress((void**)&sp_att, g_att);
    cudaGetSymbolAddress((void**)&sp_x2,  g_x2);
    cudaGetSymbolAddress((void**)&sp_mid, g_mid);

    // 1) h = LN1(x)
    ln_kernel<<<ROWS, 256>>>(x, ln1_g, ln1_b, sp_h);
    // 2) qkv = h @ w_qkv + b_qkv        [8192, 768]
    gemm_kernel<<<dim3(768/128, ROWS/128), 256>>>(sp_h, w_qkv, b_qkv, nullptr,
                                                  sp_qkv, ROWS, 768, DD, 0);
    // 3) RoPE(q), RoPE(k) in place
    rope_kernel<<<(BB*NN*2*HH*16)/256, 256>>>(sp_qkv, cosb, sinb);
    // 4) attention -> att [8192, 256]
    attn_kernel<<<dim3(NN/128, HH, BB), 128>>>(sp_qkv, sp_att);
    // 5) x2 = x + att @ w_proj + b_proj
    gemm_kernel<<<dim3(DD/128, ROWS/128), 256>>>(sp_att, w_proj, b_proj, x,
                                                 sp_x2, ROWS, DD, DD, 0);
    // 6) h = LN2(x2)
    ln_kernel<<<ROWS, 256>>>(sp_x2, ln2_g, ln2_b, sp_h);
    // 7) mid = relu(h @ w1 + b1)        [8192, 512]
    gemm_kernel<<<dim3(512/128, ROWS/128), 256>>>(sp_h, w1, b1, nullptr,
                                                  sp_mid, ROWS, 512, DD, 1);
    // 8) out = x2 + mid @ w2 + b2
    gemm_kernel<<<dim3(DD/128, ROWS/128), 256>>>(sp_mid, w2, b2, sp_x2,
                                                 out, ROWS, DD, 2*DD, 0);
}

// round 5
// speedup vs baseline: 1.0024x; 1.0024x over previous
#include <cuda_runtime.h>
#include <cuda_bf16.h>
#include <math.h>

// Shapes (fixed for this problem)
#define BB 4
#define NN 2048
#define DD 256
#define HH 8
#define dH 32
#define ROWS (BB*NN)            // 8192
#define SCALE 0.17677669529663687f   // 1/sqrt(32)

typedef unsigned long long u64;

// -------- Blackwell packed fp32 helpers (FFMA2 path, PTX-only) ------------
__device__ __forceinline__ u64 ffma2(u64 a, u64 b, u64 c) {
    u64 d; asm("fma.rn.f32x2 %0, %1, %2, %3;" : "=l"(d) : "l"(a), "l"(b), "l"(c));
    return d;
}
__device__ __forceinline__ u64 fmul2(u64 a, u64 b) {
    u64 d; asm("mul.rn.f32x2 %0, %1, %2;" : "=l"(d) : "l"(a), "l"(b));
    return d;
}
__device__ __forceinline__ u64 pack2(float lo, float hi) {
    u64 d; asm("mov.b64 %0, {%1, %2};" : "=l"(d) : "f"(lo), "f"(hi));
    return d;
}
__device__ __forceinline__ void unpack2(u64 v, float& lo, float& hi) {
    asm("mov.b64 {%0, %1}, %2;" : "=f"(lo), "=f"(hi) : "l"(v));
}

// -------------------- scratch (device globals; no allocation allowed) -----
__device__ float g_h  [ROWS*DD];
__device__ float g_qkv[ROWS*3*DD];
__device__ float g_att[ROWS*DD];
__device__ float g_x2 [ROWS*DD];
__device__ float g_mid[ROWS*2*DD];

// -------------------- LayerNorm: one block per row ------------------------
__global__ void __launch_bounds__(256) ln_kernel(
    const float* __restrict__ x, const float* __restrict__ g,
    const float* __restrict__ b, float* __restrict__ y)
{
    int row = blockIdx.x;
    int t = threadIdx.x;
    float v = x[(long)row*DD + t];
    float s = v, s2 = v*v;
    #pragma unroll
    for (int o = 16; o; o >>= 1) {
        s  += __shfl_xor_sync(0xffffffffu, s,  o);
        s2 += __shfl_xor_sync(0xffffffffu, s2, o);
    }
    __shared__ float ws[8], ws2[8];
    int w = t >> 5, l = t & 31;
    if (l == 0) { ws[w] = s; ws2[w] = s2; }
    __syncthreads();
    s = 0.f; s2 = 0.f;
    #pragma unroll
    for (int i = 0; i < 8; i++) { s += ws[i]; s2 += ws2[i]; }
    float mu  = s * (1.f/DD);
    float var = s2 * (1.f/DD) - mu*mu;
    float inv = rsqrtf(var + 1e-5f);
    y[(long)row*DD + t] = (v - mu) * inv * g[t] + b[t];
}

// -------------------- fp32 GEMM with FFMA2 mainloop -----------------------
// A: [M,K] rm, B: [K,Nn] rm, BM=BN=128, BK=16, 256 threads, 8x8 micro-tile.
__global__ void __launch_bounds__(256) gemm_kernel(
    const float* __restrict__ A, const float* __restrict__ B,
    const float* __restrict__ bias, const float* __restrict__ Res,
    float* __restrict__ C, int M, int Nn, int K, int relu)
{
    __shared__ float As[16][128];
    __shared__ u64   Bs2[16][64];      // 128 floats per row as 64 pairs

    int tid = threadIdx.x;
    int tx = tid & 15, ty = tid >> 4;
    int m0 = blockIdx.y * 128, n0 = blockIdx.x * 128;

    u64 acc2[8][4];
    #pragma unroll
    for (int i = 0; i < 8; i++)
        #pragma unroll
        for (int j = 0; j < 4; j++) acc2[i][j] = 0ull;   // (0.0f, 0.0f)

    for (int kt = 0; kt < K; kt += 16) {
        #pragma unroll
        for (int l = 0; l < 2; l++) {
            int idx = l*256 + tid;
            // A tile: 128 rows x 16 cols, stored transposed
            int r = idx >> 2, c4 = (idx & 3) << 2;
            float4 a = *(const float4*)(A + (long)(m0 + r)*K + kt + c4);
            As[c4+0][r] = a.x; As[c4+1][r] = a.y;
            As[c4+2][r] = a.z; As[c4+3][r] = a.w;
            // B tile: 16 rows x 128 cols -> pairs
            int br = idx >> 5, bc = (idx & 31) << 2;   // bc multiple of 4 floats
            *(ulonglong2*)&Bs2[br][bc >> 1] =
                *(const ulonglong2*)(B + (long)(kt + br)*Nn + n0 + bc);
        }
        __syncthreads();
        #pragma unroll
        for (int k = 0; k < 16; k++) {
            float af[8];
            *(float4*)(af)   = *(float4*)&As[k][ty*8];
            *(float4*)(af+4) = *(float4*)&As[k][ty*8+4];
            u64 bf2[4];
            ulonglong2 t0 = *(ulonglong2*)&Bs2[k][tx*4];
            ulonglong2 t1 = *(ulonglong2*)&Bs2[k][tx*4+2];
            bf2[0] = t0.x; bf2[1] = t0.y; bf2[2] = t1.x; bf2[3] = t1.y;
            u64 ad[8];
            #pragma unroll
            for (int i = 0; i < 8; i++) ad[i] = pack2(af[i], af[i]);
            #pragma unroll
            for (int i = 0; i < 8; i++)
                #pragma unroll
                for (int j = 0; j < 4; j++)
                    acc2[i][j] = ffma2(ad[i], bf2[j], acc2[i][j]);
        }
        __syncthreads();
    }

    float bv[8];
    *(float4*)(bv)   = *(const float4*)(bias + n0 + tx*8);
    *(float4*)(bv+4) = *(const float4*)(bias + n0 + tx*8 + 4);

    #pragma unroll
    for (int i = 0; i < 8; i++) {
        long row = m0 + ty*8 + i;
        float* cp = C + row*Nn + n0 + tx*8;
        float v[8];
        #pragma unroll
        for (int j = 0; j < 4; j++) unpack2(acc2[i][j], v[2*j], v[2*j+1]);
        #pragma unroll
        for (int j = 0; j < 8; j++) {
            v[j] += bv[j];
            if (relu) v[j] = fmaxf(v[j], 0.f);
        }
        if (Res) {
            const float* rp = Res + row*Nn + n0 + tx*8;
            float4 r0 = *(const float4*)rp, r1 = *(const float4*)(rp+4);
            v[0]+=r0.x; v[1]+=r0.y; v[2]+=r0.z; v[3]+=r0.w;
            v[4]+=r1.x; v[5]+=r1.y; v[6]+=r1.z; v[7]+=r1.w;
        }
        *(float4*)(cp)   = make_float4(v[0],v[1],v[2],v[3]);
        *(float4*)(cp+4) = make_float4(v[4],v[5],v[6],v[7]);
    }
}

// -------------------- RoPE in-place on q,k parts of qkv -------------------
__global__ void __launch_bounds__(256) rope_kernel(
    float* __restrict__ qkv, const float* __restrict__ cosb,
    const float* __restrict__ sinb)
{
    int gid = blockIdx.x * 256 + threadIdx.x;   // [0, B*N*2*H*16)
    int i = gid & 15;
    int h = (gid >> 4) & 7;
    int t = (gid >> 7) & 1;
    int n = (gid >> 8) & 2047;
    int b = gid >> 19;
    float c = cosb[n*16 + i], s = sinb[n*16 + i];
    long base = ((long)(b*NN + n))*(3*DD) + t*DD + h*dH + 2*i;
    float e = qkv[base], o = qkv[base+1];
    qkv[base]   = e*c - o*s;
    qkv[base+1] = e*s + o*c;
}

// -------------------- Flash attention, FFMA2 mainloop ---------------------
// 1 thread = 1 query row; K/V tiles (32 keys) staged in SMEM as f32 pairs.
__global__ void __launch_bounds__(128) attn_kernel(
    const float* __restrict__ qkv, float* __restrict__ out)
{
    int b = blockIdx.z, h = blockIdx.y;
    int tid = threadIdx.x;
    int qrow = blockIdx.x * 128 + tid;

    const float* qp = qkv + ((long)(b*NN + qrow))*(3*DD) + h*dH;
    u64 q2[16];
    #pragma unroll
    for (int i = 0; i < 8; i++) {
        float4 t4 = *(const float4*)(qp + i*4);
        q2[i*2]   = pack2(t4.x*SCALE, t4.y*SCALE);
        q2[i*2+1] = pack2(t4.z*SCALE, t4.w*SCALE);
    }
    u64 o2[16];
    #pragma unroll
    for (int i = 0; i < 16; i++) o2[i] = 0ull;
    float m = -1e30f, s = 0.f;

    __shared__ u64 ks[32][16];   // 32 keys x 32 floats (16 pairs)
    __shared__ u64 vs[32][16];

    const float* kbase = qkv + (long)b*NN*(3*DD) + DD   + h*dH;
    const float* vbase = qkv + (long)b*NN*(3*DD) + 2*DD + h*dH;

    for (int jt = 0; jt < NN/32; jt++) {
        __syncthreads();
        #pragma unroll
        for (int l = 0; l < 2; l++) {
            int idx = l*128 + tid;
            int key = idx >> 3, p2 = (idx & 7) << 1;  // pair index 0..15 step 2
            long off = (long)(jt*32 + key)*(3*DD) + (p2 << 1);
            *(ulonglong2*)&ks[key][p2] = *(const ulonglong2*)(kbase + off);
            *(ulonglong2*)&vs[key][p2] = *(const ulonglong2*)(vbase + off);
        }
        __syncthreads();

        float sc[32];
        float tmax = -1e30f;
        #pragma unroll
        for (int j = 0; j < 32; j++) {
            u64 a0 = 0ull, a1 = 0ull;
            #pragma unroll
            for (int dd = 0; dd < 8; dd++) {
                ulonglong2 kv = *(const ulonglong2*)&ks[j][dd*2];
                a0 = ffma2(q2[dd*2],   kv.x, a0);
                a1 = ffma2(q2[dd*2+1], kv.y, a1);
            }
            float x0, x1, y0, y1;
            unpack2(a0, x0, x1); unpack2(a1, y0, y1);
            float v = (x0+x1) + (y0+y1);
            sc[j] = v;
            tmax = fmaxf(tmax, v);
        }
        float nm = fmaxf(m, tmax);
        float corr = __expf(m - nm);
        s *= corr;
        u64 cp2 = pack2(corr, corr);
        #pragma unroll
        for (int i = 0; i < 16; i++) o2[i] = fmul2(cp2, o2[i]);
        #pragma unroll
        for (int j = 0; j < 32; j++) {
            float p = __expf(sc[j] - nm);
            s += p;
            u64 pp = pack2(p, p);
            #pragma unroll
            for (int dd = 0; dd < 8; dd++) {
                ulonglong2 vv = *(const ulonglong2*)&vs[j][dd*2];
                o2[dd*2]   = ffma2(pp, vv.x, o2[dd*2]);
                o2[dd*2+1] = ffma2(pp, vv.y, o2[dd*2+1]);
            }
        }
        m = nm;
    }

    float inv = 1.f / s;
    u64 ip2 = pack2(inv, inv);
    float* op = out + ((long)(b*NN + qrow))*DD + h*dH;
    #pragma unroll
    for (int i = 0; i < 8; i++) {
        ulonglong2 t2;
        t2.x = fmul2(ip2, o2[i*2]);
        t2.y = fmul2(ip2, o2[i*2+1]);
        *(ulonglong2*)(op + i*4) = t2;
    }
}

// -------------------- launch ----------------------------------------------
extern "C" void kernel_launch(void* const* d_in, const int* in_sizes, int n_in,
                              void* d_out, int out_size)
{
    const float* x      = (const float*)d_in[0];
    const float* cosb   = (const float*)d_in[1];
    const float* sinb   = (const float*)d_in[2];
    const float* w_qkv  = (const float*)d_in[3];
    const float* b_qkv  = (const float*)d_in[4];
    const float* w_proj = (const float*)d_in[5];
    const float* b_proj = (const float*)d_in[6];
    const float* ln1_g  = (const float*)d_in[7];
    const float* ln1_b  = (const float*)d_in[8];
    const float* ln2_g  = (const float*)d_in[9];
    const float* ln2_b  = (const float*)d_in[10];
    const float* w1     = (const float*)d_in[11];
    const float* b1     = (const float*)d_in[12];
    const float* w2     = (const float*)d_in[13];
    const float* b2     = (const float*)d_in[14];
    float* out = (float*)d_out;

    float *sp_h, *sp_qkv, *sp_att, *sp_x2, *sp_mid;
    cudaGetSymbolAddress((void**)&sp_h,   g_h);
    cudaGetSymbolAddress((void**)&sp_qkv, g_qkv);
    cudaGetSymbolAddress((void**)&sp_att, g_att);
    cudaGetSymbolAddress((void**)&sp_x2,  g_x2);
    cudaGetSymbolAddress((void**)&sp_mid, g_mid);

    // 1) h = LN1(x)
    ln_kernel<<<ROWS, 256>>>(x, ln1_g, ln1_b, sp_h);
    // 2) qkv = h @ w_qkv + b_qkv        [8192, 768]
    gemm_kernel<<<dim3(768/128, ROWS/128), 256>>>(sp_h, w_qkv, b_qkv, nullptr,
                                                  sp_qkv, ROWS, 768, DD, 0);
    // 3) RoPE(q), RoPE(k) in place
    rope_kernel<<<(BB*NN*2*HH*16)/256, 256>>>(sp_qkv, cosb, sinb);
    // 4) attention -> att [8192, 256]
    attn_kernel<<<dim3(NN/128, HH, BB), 128>>>(sp_qkv, sp_att);
    // 5) x2 = x + att @ w_proj + b_proj
    gemm_kernel<<<dim3(DD/128, ROWS/128), 256>>>(sp_att, w_proj, b_proj, x,
                                                 sp_x2, ROWS, DD, DD, 0);
    // 6) h = LN2(x2)
    ln_kernel<<<ROWS, 256>>>(sp_x2, ln2_g, ln2_b, sp_h);
    // 7) mid = relu(h @ w1 + b1)        [8192, 512]
    gemm_kernel<<<dim3(512/128, ROWS/128), 256>>>(sp_h, w1, b1, nullptr,
                                                  sp_mid, ROWS, 512, DD, 1);
    // 8) out = x2 + mid @ w2 + b2
    gemm_kernel<<<dim3(DD/128, ROWS/128), 256>>>(sp_mid, w2, b2, sp_x2,
                                                 out, ROWS, DD, 2*DD, 0);
}

// round 9
// speedup vs baseline: 2.2100x; 2.2048x over previous
#include <cuda_runtime.h>
#include <cuda_bf16.h>
#include <math.h>

// Shapes (fixed for this problem)
#define BB 4
#define NN 2048
#define DD 256
#define HH 8
#define dH 32
#define ROWS (BB*NN)            // 8192
#define SCALE 0.17677669529663687f   // 1/sqrt(32)

typedef unsigned long long u64;
typedef unsigned int u32;

// -------- Blackwell packed fp32 helpers (FFMA2 path, PTX-only) ------------
__device__ __forceinline__ u64 ffma2(u64 a, u64 b, u64 c) {
    u64 d; asm("fma.rn.f32x2 %0, %1, %2, %3;" : "=l"(d) : "l"(a), "l"(b), "l"(c));
    return d;
}
__device__ __forceinline__ u64 pack2(float lo, float hi) {
    u64 d; asm("mov.b64 %0, {%1, %2};" : "=l"(d) : "f"(lo), "f"(hi));
    return d;
}
__device__ __forceinline__ void unpack2(u64 v, float& lo, float& hi) {
    asm("mov.b64 {%0, %1}, %2;" : "=f"(lo), "=f"(hi) : "l"(v));
}

// -------- tf32 mma.sync helpers -------------------------------------------
__device__ __forceinline__ u32 f2tf(float f) {
    u32 u; asm("cvt.rna.tf32.f32 %0, %1;" : "=r"(u) : "f"(f));
    return u;
}
__device__ __forceinline__ void mma_tf32(
    float& d0, float& d1, float& d2, float& d3,
    u32 a0, u32 a1, u32 a2, u32 a3, u32 b0, u32 b1)
{
    asm("mma.sync.aligned.m16n8k8.row.col.f32.tf32.tf32.f32 "
        "{%0,%1,%2,%3}, {%4,%5,%6,%7}, {%8,%9}, {%0,%1,%2,%3};"
        : "+f"(d0), "+f"(d1), "+f"(d2), "+f"(d3)
        : "r"(a0), "r"(a1), "r"(a2), "r"(a3), "r"(b0), "r"(b1));
}

// -------------------- scratch (device globals; no allocation allowed) -----
__device__ float g_h  [ROWS*DD];
__device__ float g_qkv[ROWS*3*DD];
__device__ float g_att[ROWS*DD];
__device__ float g_x2 [ROWS*DD];
__device__ float g_mid[ROWS*2*DD];

// -------------------- LayerNorm: one block per row ------------------------
__global__ void __launch_bounds__(256) ln_kernel(
    const float* __restrict__ x, const float* __restrict__ g,
    const float* __restrict__ b, float* __restrict__ y)
{
    int row = blockIdx.x;
    int t = threadIdx.x;
    float v = x[(long)row*DD + t];
    float s = v, s2 = v*v;
    #pragma unroll
    for (int o = 16; o; o >>= 1) {
        s  += __shfl_xor_sync(0xffffffffu, s,  o);
        s2 += __shfl_xor_sync(0xffffffffu, s2, o);
    }
    __shared__ float ws[8], ws2[8];
    int w = t >> 5, l = t & 31;
    if (l == 0) { ws[w] = s; ws2[w] = s2; }
    __syncthreads();
    s = 0.f; s2 = 0.f;
    #pragma unroll
    for (int i = 0; i < 8; i++) { s += ws[i]; s2 += ws2[i]; }
    float mu  = s * (1.f/DD);
    float var = s2 * (1.f/DD) - mu*mu;
    float inv = rsqrtf(var + 1e-5f);
    y[(long)row*DD + t] = (v - mu) * inv * g[t] + b[t];
}

// -------------------- fp32 GEMM with FFMA2 mainloop -----------------------
__global__ void __launch_bounds__(256) gemm_kernel(
    const float* __restrict__ A, const float* __restrict__ B,
    const float* __restrict__ bias, const float* __restrict__ Res,
    float* __restrict__ C, int M, int Nn, int K, int relu)
{
    __shared__ float As[16][128];
    __shared__ u64   Bs2[16][64];

    int tid = threadIdx.x;
    int tx = tid & 15, ty = tid >> 4;
    int m0 = blockIdx.y * 128, n0 = blockIdx.x * 128;

    u64 acc2[8][4];
    #pragma unroll
    for (int i = 0; i < 8; i++)
        #pragma unroll
        for (int j = 0; j < 4; j++) acc2[i][j] = 0ull;

    for (int kt = 0; kt < K; kt += 16) {
        #pragma unroll
        for (int l = 0; l < 2; l++) {
            int idx = l*256 + tid;
            int r = idx >> 2, c4 = (idx & 3) << 2;
            float4 a = *(const float4*)(A + (long)(m0 + r)*K + kt + c4);
            As[c4+0][r] = a.x; As[c4+1][r] = a.y;
            As[c4+2][r] = a.z; As[c4+3][r] = a.w;
            int br = idx >> 5, bc = (idx & 31) << 2;
            *(ulonglong2*)&Bs2[br][bc >> 1] =
                *(const ulonglong2*)(B + (long)(kt + br)*Nn + n0 + bc);
        }
        __syncthreads();
        #pragma unroll
        for (int k = 0; k < 16; k++) {
            float af[8];
            *(float4*)(af)   = *(float4*)&As[k][ty*8];
            *(float4*)(af+4) = *(float4*)&As[k][ty*8+4];
            u64 bf2[4];
            ulonglong2 t0 = *(ulonglong2*)&Bs2[k][tx*4];
            ulonglong2 t1 = *(ulonglong2*)&Bs2[k][tx*4+2];
            bf2[0] = t0.x; bf2[1] = t0.y; bf2[2] = t1.x; bf2[3] = t1.y;
            u64 ad[8];
            #pragma unroll
            for (int i = 0; i < 8; i++) ad[i] = pack2(af[i], af[i]);
            #pragma unroll
            for (int i = 0; i < 8; i++)
                #pragma unroll
                for (int j = 0; j < 4; j++)
                    acc2[i][j] = ffma2(ad[i], bf2[j], acc2[i][j]);
        }
        __syncthreads();
    }

    float bv[8];
    *(float4*)(bv)   = *(const float4*)(bias + n0 + tx*8);
    *(float4*)(bv+4) = *(const float4*)(bias + n0 + tx*8 + 4);

    #pragma unroll
    for (int i = 0; i < 8; i++) {
        long row = m0 + ty*8 + i;
        float* cp = C + row*Nn + n0 + tx*8;
        float v[8];
        #pragma unroll
        for (int j = 0; j < 4; j++) unpack2(acc2[i][j], v[2*j], v[2*j+1]);
        #pragma unroll
        for (int j = 0; j < 8; j++) {
            v[j] += bv[j];
            if (relu) v[j] = fmaxf(v[j], 0.f);
        }
        if (Res) {
            const float* rp = Res + row*Nn + n0 + tx*8;
            float4 r0 = *(const float4*)rp, r1 = *(const float4*)(rp+4);
            v[0]+=r0.x; v[1]+=r0.y; v[2]+=r0.z; v[3]+=r0.w;
            v[4]+=r1.x; v[5]+=r1.y; v[6]+=r1.z; v[7]+=r1.w;
        }
        *(float4*)(cp)   = make_float4(v[0],v[1],v[2],v[3]);
        *(float4*)(cp+4) = make_float4(v[4],v[5],v[6],v[7]);
    }
}

// -------------------- RoPE in-place on q,k parts of qkv -------------------
__global__ void __launch_bounds__(256) rope_kernel(
    float* __restrict__ qkv, const float* __restrict__ cosb,
    const float* __restrict__ sinb)
{
    int gid = blockIdx.x * 256 + threadIdx.x;
    int i = gid & 15;
    int h = (gid >> 4) & 7;
    int t = (gid >> 7) & 1;
    int n = (gid >> 8) & 2047;
    int b = gid >> 19;
    float c = cosb[n*16 + i], s = sinb[n*16 + i];
    long base = ((long)(b*NN + n))*(3*DD) + t*DD + h*dH + 2*i;
    float e = qkv[base], o = qkv[base+1];
    qkv[base]   = e*c - o*s;
    qkv[base+1] = e*s + o*c;
}

// -------------------- Flash attention with mma.sync tf32 ------------------
// CTA = 4 warps, 64 q-rows (16/warp). Key tiles of 64 in SMEM [64][36] pad.
// QK: m16n8k8 tf32 (A=Q frags from regs, B=K frags from SMEM).
// Softmax in C-fragment registers; online rescale of O frags.
// PV: P C-frags reused DIRECTLY as A-frags (cols 2j,2j+1 -> j,j+4), with V
// rows read in permuted order key = 8*kk + 2c (+1) so positions match.
__global__ void __launch_bounds__(128) attn_mma_kernel(
    const float* __restrict__ qkv, float* __restrict__ out)
{
    int bh = blockIdx.y;                 // b*8 + h
    int b = bh >> 3, h = bh & 7;
    int warp = threadIdx.x >> 5, lane = threadIdx.x & 31;
    int g = lane >> 2, c = lane & 3;
    int q0 = blockIdx.x * 64 + warp * 16;

    __shared__ float Ks[64*36];
    __shared__ float Vs[64*36];

    const float* qb = qkv + (long)(b*NN)*(3*DD) + h*dH;       // + row*768
    const float* kb = qb + DD;
    const float* vb = qb + 2*DD;

    // ---- Q fragments (scaled, tf32), 4 k-steps over d=32 ----
    u32 qa[4][4];
    #pragma unroll
    for (int kk = 0; kk < 4; kk++) {
        int col = kk*8 + c;
        qa[kk][0] = f2tf(qb[(long)(q0+g  )*768 + col    ] * SCALE);
        qa[kk][1] = f2tf(qb[(long)(q0+g+8)*768 + col    ] * SCALE);
        qa[kk][2] = f2tf(qb[(long)(q0+g  )*768 + col + 4] * SCALE);
        qa[kk][3] = f2tf(qb[(long)(q0+g+8)*768 + col + 4] * SCALE);
    }

    float O[4][4];
    #pragma unroll
    for (int n = 0; n < 4; n++)
        #pragma unroll
        for (int i = 0; i < 4; i++) O[n][i] = 0.f;
    float m0 = -1e30f, m1 = -1e30f, l0 = 0.f, l1 = 0.f;

    for (int jt = 0; jt < NN/64; jt++) {
        __syncthreads();
        // stage K,V tile: 64 keys x 32 floats, padded stride 36
        #pragma unroll
        for (int it = 0; it < 4; it++) {
            int i = it*128 + threadIdx.x;
            int key = i >> 3, d4 = (i & 7) << 2;
            long goff = (long)(jt*64 + key)*768 + d4;
            *(float4*)&Ks[key*36 + d4] = *(const float4*)(kb + goff);
            *(float4*)&Vs[key*36 + d4] = *(const float4*)(vb + goff);
        }
        __syncthreads();

        // ---- S = Q K^T : 8 key-subtiles x 4 k-steps ----
        float s[8][4];
        #pragma unroll
        for (int n = 0; n < 8; n++) {
            s[n][0] = s[n][1] = s[n][2] = s[n][3] = 0.f;
            #pragma unroll
            for (int kk = 0; kk < 4; kk++) {
                u32 b0 = f2tf(Ks[(n*8 + g)*36 + kk*8 + c    ]);
                u32 b1 = f2tf(Ks[(n*8 + g)*36 + kk*8 + c + 4]);
                mma_tf32(s[n][0], s[n][1], s[n][2], s[n][3],
                         qa[kk][0], qa[kk][1], qa[kk][2], qa[kk][3], b0, b1);
            }
        }

        // ---- online softmax (rows g and g+8) ----
        float t0 = -1e30f, t1 = -1e30f;
        #pragma unroll
        for (int n = 0; n < 8; n++) {
            t0 = fmaxf(t0, fmaxf(s[n][0], s[n][1]));
            t1 = fmaxf(t1, fmaxf(s[n][2], s[n][3]));
        }
        #pragma unroll
        for (int o = 1; o <= 2; o <<= 1) {
            t0 = fmaxf(t0, __shfl_xor_sync(0xffffffffu, t0, o));
            t1 = fmaxf(t1, __shfl_xor_sync(0xffffffffu, t1, o));
        }
        float nm0 = fmaxf(m0, t0), nm1 = fmaxf(m1, t1);
        float cor0 = __expf(m0 - nm0), cor1 = __expf(m1 - nm1);
        l0 *= cor0; l1 *= cor1;
        #pragma unroll
        for (int n = 0; n < 4; n++) {
            O[n][0] *= cor0; O[n][1] *= cor0;
            O[n][2] *= cor1; O[n][3] *= cor1;
        }
        float rs0 = 0.f, rs1 = 0.f;
        #pragma unroll
        for (int n = 0; n < 8; n++) {
            s[n][0] = __expf(s[n][0] - nm0);
            s[n][1] = __expf(s[n][1] - nm0);
            s[n][2] = __expf(s[n][2] - nm1);
            s[n][3] = __expf(s[n][3] - nm1);
            rs0 += s[n][0] + s[n][1];
            rs1 += s[n][2] + s[n][3];
        }
        #pragma unroll
        for (int o = 1; o <= 2; o <<= 1) {
            rs0 += __shfl_xor_sync(0xffffffffu, rs0, o);
            rs1 += __shfl_xor_sync(0xffffffffu, rs1, o);
        }
        l0 += rs0; l1 += rs1;
        m0 = nm0; m1 = nm1;

        // ---- O += P V : 8 key-groups x 4 d-subtiles ----
        // A-frag = C-frag of S (cols 2j,2j+1 -> A cols j, j+4);
        // V rows permuted: key = 8kk + 2c (b0), 8kk + 2c + 1 (b1).
        #pragma unroll
        for (int kk = 0; kk < 8; kk++) {
            u32 pa0 = f2tf(s[kk][0]);
            u32 pa1 = f2tf(s[kk][2]);
            u32 pa2 = f2tf(s[kk][1]);
            u32 pa3 = f2tf(s[kk][3]);
            #pragma unroll
            for (int n = 0; n < 4; n++) {
                u32 vb0 = f2tf(Vs[(kk*8 + 2*c    )*36 + n*8 + g]);
                u32 vb1 = f2tf(Vs[(kk*8 + 2*c + 1)*36 + n*8 + g]);
                mma_tf32(O[n][0], O[n][1], O[n][2], O[n][3],
                         pa0, pa1, pa2, pa3, vb0, vb1);
            }
        }
    }

    // ---- epilogue ----
    float inv0 = 1.f / l0, inv1 = 1.f / l1;
    #pragma unroll
    for (int n = 0; n < 4; n++) {
        long r0o = ((long)(b*NN + q0 + g    ))*DD + h*dH + n*8 + 2*c;
        long r1o = ((long)(b*NN + q0 + g + 8))*DD + h*dH + n*8 + 2*c;
        *(float2*)(out + r0o) = make_float2(O[n][0]*inv0, O[n][1]*inv0);
        *(float2*)(out + r1o) = make_float2(O[n][2]*inv1, O[n][3]*inv1);
    }
}

// -------------------- launch ----------------------------------------------
extern "C" void kernel_launch(void* const* d_in, const int* in_sizes, int n_in,
                              void* d_out, int out_size)
{
    const float* x      = (const float*)d_in[0];
    const float* cosb   = (const float*)d_in[1];
    const float* sinb   = (const float*)d_in[2];
    const float* w_qkv  = (const float*)d_in[3];
    const float* b_qkv  = (const float*)d_in[4];
    const float* w_proj = (const float*)d_in[5];
    const float* b_proj = (const float*)d_in[6];
    const float* ln1_g  = (const float*)d_in[7];
    const float* ln1_b  = (const float*)d_in[8];
    const float* ln2_g  = (const float*)d_in[9];
    const float* ln2_b  = (const float*)d_in[10];
    const float* w1     = (const float*)d_in[11];
    const float* b1     = (const float*)d_in[12];
    const float* w2     = (const float*)d_in[13];
    const float* b2     = (const float*)d_in[14];
    float* out = (float*)d_out;

    float *sp_h, *sp_qkv, *sp_att, *sp_x2, *sp_mid;
    cudaGetSymbolAddress((void**)&sp_h,   g_h);
    cudaGetSymbolAddress((void**)&sp_qkv, g_qkv);
    cudaGetSymbolAddress((void**)&sp_att, g_att);
    cudaGetSymbolAddress((void**)&sp_x2,  g_x2);
    cudaGetSymbolAddress((void**)&sp_mid, g_mid);

    // 1) h = LN1(x)
    ln_kernel<<<ROWS, 256>>>(x, ln1_g, ln1_b, sp_h);
    // 2) qkv = h @ w_qkv + b_qkv        [8192, 768]
    gemm_kernel<<<dim3(768/128, ROWS/128), 256>>>(sp_h, w_qkv, b_qkv, nullptr,
                                                  sp_qkv, ROWS, 768, DD, 0);
    // 3) RoPE(q), RoPE(k) in place
    rope_kernel<<<(BB*NN*2*HH*16)/256, 256>>>(sp_qkv, cosb, sinb);
    // 4) attention -> att [8192, 256]  (tensor-core path)
    attn_mma_kernel<<<dim3(NN/64, BB*HH), 128>>>(sp_qkv, sp_att);
    // 5) x2 = x + att @ w_proj + b_proj
    gemm_kernel<<<dim3(DD/128, ROWS/128), 256>>>(sp_att, w_proj, b_proj, x,
                                                 sp_x2, ROWS, DD, DD, 0);
    // 6) h = LN2(x2)
    ln_kernel<<<ROWS, 256>>>(sp_x2, ln2_g, ln2_b, sp_h);
    // 7) mid = relu(h @ w1 + b1)        [8192, 512]
    gemm_kernel<<<dim3(512/128, ROWS/128), 256>>>(sp_h, w1, b1, nullptr,
                                                  sp_mid, ROWS, 512, DD, 1);
    // 8) out = x2 + mid @ w2 + b2
    gemm_kernel<<<dim3(DD/128, ROWS/128), 256>>>(sp_mid, w2, b2, sp_x2,
                                                 out, ROWS, DD, 2*DD, 0);
}

// round 10
// speedup vs baseline: 3.5705x; 1.6156x over previous
#include <cuda_runtime.h>
#include <cuda_bf16.h>
#include <math.h>

// Shapes (fixed for this problem)
#define BB 4
#define NN 2048
#define DD 256
#define HH 8
#define dH 32
#define ROWS (BB*NN)            // 8192
#define SCALE 0.17677669529663687f   // 1/sqrt(32)

typedef unsigned long long u64;
typedef unsigned int u32;

// -------- tf32 mma.sync helpers -------------------------------------------
__device__ __forceinline__ u32 f2tf(float f) {
    u32 u; asm("cvt.rna.tf32.f32 %0, %1;" : "=r"(u) : "f"(f));
    return u;
}
__device__ __forceinline__ void mma_tf32(
    float& d0, float& d1, float& d2, float& d3,
    u32 a0, u32 a1, u32 a2, u32 a3, u32 b0, u32 b1)
{
    asm("mma.sync.aligned.m16n8k8.row.col.f32.tf32.tf32.f32 "
        "{%0,%1,%2,%3}, {%4,%5,%6,%7}, {%8,%9}, {%0,%1,%2,%3};"
        : "+f"(d0), "+f"(d1), "+f"(d2), "+f"(d3)
        : "r"(a0), "r"(a1), "r"(a2), "r"(a3), "r"(b0), "r"(b1));
}

// -------------------- scratch (device globals; no allocation allowed) -----
__device__ float g_h  [ROWS*DD];
__device__ float g_qkv[ROWS*3*DD];
__device__ float g_att[ROWS*DD];
__device__ float g_x2 [ROWS*DD];
__device__ float g_mid[ROWS*2*DD];

// -------------------- LayerNorm: one block per row ------------------------
__global__ void __launch_bounds__(256) ln_kernel(
    const float* __restrict__ x, const float* __restrict__ g,
    const float* __restrict__ b, float* __restrict__ y)
{
    int row = blockIdx.x;
    int t = threadIdx.x;
    float v = x[(long)row*DD + t];
    float s = v, s2 = v*v;
    #pragma unroll
    for (int o = 16; o; o >>= 1) {
        s  += __shfl_xor_sync(0xffffffffu, s,  o);
        s2 += __shfl_xor_sync(0xffffffffu, s2, o);
    }
    __shared__ float ws[8], ws2[8];
    int w = t >> 5, l = t & 31;
    if (l == 0) { ws[w] = s; ws2[w] = s2; }
    __syncthreads();
    s = 0.f; s2 = 0.f;
    #pragma unroll
    for (int i = 0; i < 8; i++) { s += ws[i]; s2 += ws2[i]; }
    float mu  = s * (1.f/DD);
    float var = s2 * (1.f/DD) - mu*mu;
    float inv = rsqrtf(var + 1e-5f);
    y[(long)row*DD + t] = (v - mu) * inv * g[t] + b[t];
}

// -------------------- tf32 tensor-core GEMM -------------------------------
// C[M,Nn] = A[M,K] @ B[K,Nn] (+bias)(+relu)(+Res). 256 thr, tile 128x128,
// BK=16. Warp grid 2(M)x4(N): each warp 64x32 = 4x4 m16n8k8 tiles.
// As: swizzled [row][16] words, chunk' = chunk ^ ((row>>1)&3)  (conflict-free
//     for both STS.128 staging and quad A-frag loads).
// Bs: [16][136] words (136 % 32 == 8 -> bank = 8c+g, conflict-free).
#define GS 136
__global__ void __launch_bounds__(256) gemm_tc_kernel(
    const float* __restrict__ A, const float* __restrict__ B,
    const float* __restrict__ bias, const float* __restrict__ Res,
    float* __restrict__ C, int M, int Nn, int K, int relu)
{
    __shared__ u32 As[128*16];
    __shared__ u32 Bs[16*GS];

    int tid = threadIdx.x;
    int lane = tid & 31, warp = tid >> 5;
    int g = lane >> 2, c = lane & 3;
    int wm = warp & 1, wn = warp >> 1;
    int m0 = blockIdx.y * 128, n0 = blockIdx.x * 128;

    float acc[4][4][4];
    #pragma unroll
    for (int mt = 0; mt < 4; mt++)
        #pragma unroll
        for (int nt = 0; nt < 4; nt++)
            #pragma unroll
            for (int i = 0; i < 4; i++) acc[mt][nt][i] = 0.f;

    int xr = (g >> 1) & 3;

    for (int kt = 0; kt < K; kt += 16) {
        #pragma unroll
        for (int l = 0; l < 2; l++) {
            int idx = l*256 + tid;
            // A tile: 128 rows x 16 cols
            int r = idx >> 2, ch = idx & 3;
            float4 av = *(const float4*)(A + (long)(m0 + r)*K + kt + ch*4);
            uint4 aw = make_uint4(f2tf(av.x), f2tf(av.y), f2tf(av.z), f2tf(av.w));
            *(uint4*)&As[r*16 + (ch ^ ((r >> 1) & 3))*4] = aw;
            // B tile: 16 rows x 128 cols
            int br = idx >> 5, bc = (idx & 31) << 2;
            float4 bv4 = *(const float4*)(B + (long)(kt + br)*Nn + n0 + bc);
            uint4 bw = make_uint4(f2tf(bv4.x), f2tf(bv4.y), f2tf(bv4.z), f2tf(bv4.w));
            *(uint4*)&Bs[br*GS + bc] = bw;
        }
        __syncthreads();
        #pragma unroll
        for (int kk = 0; kk < 2; kk++) {
            u32 bf[4][2];
            #pragma unroll
            for (int nt = 0; nt < 4; nt++) {
                int n = wn*32 + nt*8 + g;
                bf[nt][0] = Bs[(kk*8 + c    )*GS + n];
                bf[nt][1] = Bs[(kk*8 + c + 4)*GS + n];
            }
            int off0 = ((2*kk    ) ^ xr)*4 + c;
            int off1 = ((2*kk + 1) ^ xr)*4 + c;
            #pragma unroll
            for (int mt = 0; mt < 4; mt++) {
                int row = wm*64 + mt*16 + g;
                u32 a0 = As[ row     *16 + off0];
                u32 a1 = As[(row + 8)*16 + off0];
                u32 a2 = As[ row     *16 + off1];
                u32 a3 = As[(row + 8)*16 + off1];
                #pragma unroll
                for (int nt = 0; nt < 4; nt++)
                    mma_tf32(acc[mt][nt][0], acc[mt][nt][1],
                             acc[mt][nt][2], acc[mt][nt][3],
                             a0, a1, a2, a3, bf[nt][0], bf[nt][1]);
            }
        }
        __syncthreads();
    }

    // epilogue
    #pragma unroll
    for (int nt = 0; nt < 4; nt++) {
        int col = n0 + wn*32 + nt*8 + 2*c;
        float2 bv = *(const float2*)(bias + col);
        #pragma unroll
        for (int mt = 0; mt < 4; mt++) {
            long r0 = m0 + wm*64 + mt*16 + g;
            long r1 = r0 + 8;
            float v0 = acc[mt][nt][0] + bv.x;
            float v1 = acc[mt][nt][1] + bv.y;
            float v2 = acc[mt][nt][2] + bv.x;
            float v3 = acc[mt][nt][3] + bv.y;
            if (relu) {
                v0 = fmaxf(v0, 0.f); v1 = fmaxf(v1, 0.f);
                v2 = fmaxf(v2, 0.f); v3 = fmaxf(v3, 0.f);
            }
            if (Res) {
                float2 q0 = *(const float2*)(Res + r0*Nn + col);
                float2 q1 = *(const float2*)(Res + r1*Nn + col);
                v0 += q0.x; v1 += q0.y; v2 += q1.x; v3 += q1.y;
            }
            *(float2*)(C + r0*Nn + col) = make_float2(v0, v1);
            *(float2*)(C + r1*Nn + col) = make_float2(v2, v3);
        }
    }
}

// -------------------- RoPE in-place on q,k parts of qkv -------------------
__global__ void __launch_bounds__(256) rope_kernel(
    float* __restrict__ qkv, const float* __restrict__ cosb,
    const float* __restrict__ sinb)
{
    int gid = blockIdx.x * 256 + threadIdx.x;
    int i = gid & 15;
    int h = (gid >> 4) & 7;
    int t = (gid >> 7) & 1;
    int n = (gid >> 8) & 2047;
    int b = gid >> 19;
    float c = cosb[n*16 + i], s = sinb[n*16 + i];
    long base = ((long)(b*NN + n))*(3*DD) + t*DD + h*dH + 2*i;
    float e = qkv[base], o = qkv[base+1];
    qkv[base]   = e*c - o*s;
    qkv[base+1] = e*s + o*c;
}

// -------------------- Flash attention with mma.sync tf32 ------------------
// K/V pre-converted to tf32 at staging (u32 SMEM) -> no cvt in hot loop.
__global__ void __launch_bounds__(128) attn_mma_kernel(
    const float* __restrict__ qkv, float* __restrict__ out)
{
    int bh = blockIdx.y;                 // b*8 + h
    int b = bh >> 3, h = bh & 7;
    int warp = threadIdx.x >> 5, lane = threadIdx.x & 31;
    int g = lane >> 2, c = lane & 3;
    int q0 = blockIdx.x * 64 + warp * 16;

    __shared__ u32 Ks[64*36];
    __shared__ u32 Vs[64*36];

    const float* qb = qkv + (long)(b*NN)*(3*DD) + h*dH;       // + row*768
    const float* kb = qb + DD;
    const float* vb = qb + 2*DD;

    // ---- Q fragments (scaled, tf32), 4 k-steps over d=32 ----
    u32 qa[4][4];
    #pragma unroll
    for (int kk = 0; kk < 4; kk++) {
        int col = kk*8 + c;
        qa[kk][0] = f2tf(qb[(long)(q0+g  )*768 + col    ] * SCALE);
        qa[kk][1] = f2tf(qb[(long)(q0+g+8)*768 + col    ] * SCALE);
        qa[kk][2] = f2tf(qb[(long)(q0+g  )*768 + col + 4] * SCALE);
        qa[kk][3] = f2tf(qb[(long)(q0+g+8)*768 + col + 4] * SCALE);
    }

    float O[4][4];
    #pragma unroll
    for (int n = 0; n < 4; n++)
        #pragma unroll
        for (int i = 0; i < 4; i++) O[n][i] = 0.f;
    float m0 = -1e30f, m1 = -1e30f, l0 = 0.f, l1 = 0.f;

    for (int jt = 0; jt < NN/64; jt++) {
        __syncthreads();
        // stage K,V tile: 64 keys x 32 floats, stride 36, tf32-converted
        #pragma unroll
        for (int it = 0; it < 4; it++) {
            int i = it*128 + threadIdx.x;
            int key = i >> 3, d4 = (i & 7) << 2;
            long goff = (long)(jt*64 + key)*768 + d4;
            float4 kv = *(const float4*)(kb + goff);
            float4 vv = *(const float4*)(vb + goff);
            *(uint4*)&Ks[key*36 + d4] =
                make_uint4(f2tf(kv.x), f2tf(kv.y), f2tf(kv.z), f2tf(kv.w));
            *(uint4*)&Vs[key*36 + d4] =
                make_uint4(f2tf(vv.x), f2tf(vv.y), f2tf(vv.z), f2tf(vv.w));
        }
        __syncthreads();

        // ---- S = Q K^T : 8 key-subtiles x 4 k-steps ----
        float s[8][4];
        #pragma unroll
        for (int n = 0; n < 8; n++) {
            s[n][0] = s[n][1] = s[n][2] = s[n][3] = 0.f;
            #pragma unroll
            for (int kk = 0; kk < 4; kk++) {
                u32 b0 = Ks[(n*8 + g)*36 + kk*8 + c    ];
                u32 b1 = Ks[(n*8 + g)*36 + kk*8 + c + 4];
                mma_tf32(s[n][0], s[n][1], s[n][2], s[n][3],
                         qa[kk][0], qa[kk][1], qa[kk][2], qa[kk][3], b0, b1);
            }
        }

        // ---- online softmax (rows g and g+8) ----
        float t0 = -1e30f, t1 = -1e30f;
        #pragma unroll
        for (int n = 0; n < 8; n++) {
            t0 = fmaxf(t0, fmaxf(s[n][0], s[n][1]));
            t1 = fmaxf(t1, fmaxf(s[n][2], s[n][3]));
        }
        #pragma unroll
        for (int o = 1; o <= 2; o <<= 1) {
            t0 = fmaxf(t0, __shfl_xor_sync(0xffffffffu, t0, o));
            t1 = fmaxf(t1, __shfl_xor_sync(0xffffffffu, t1, o));
        }
        float nm0 = fmaxf(m0, t0), nm1 = fmaxf(m1, t1);
        float cor0 = __expf(m0 - nm0), cor1 = __expf(m1 - nm1);
        l0 *= cor0; l1 *= cor1;
        #pragma unroll
        for (int n = 0; n < 4; n++) {
            O[n][0] *= cor0; O[n][1] *= cor0;
            O[n][2] *= cor1; O[n][3] *= cor1;
        }
        float rs0 = 0.f, rs1 = 0.f;
        #pragma unroll
        for (int n = 0; n < 8; n++) {
            s[n][0] = __expf(s[n][0] - nm0);
            s[n][1] = __expf(s[n][1] - nm0);
            s[n][2] = __expf(s[n][2] - nm1);
            s[n][3] = __expf(s[n][3] - nm1);
            rs0 += s[n][0] + s[n][1];
            rs1 += s[n][2] + s[n][3];
        }
        #pragma unroll
        for (int o = 1; o <= 2; o <<= 1) {
            rs0 += __shfl_xor_sync(0xffffffffu, rs0, o);
            rs1 += __shfl_xor_sync(0xffffffffu, rs1, o);
        }
        l0 += rs0; l1 += rs1;
        m0 = nm0; m1 = nm1;

        // ---- O += P V : P C-frags reused as A-frags; V rows permuted ----
        #pragma unroll
        for (int kk = 0; kk < 8; kk++) {
            u32 pa0 = f2tf(s[kk][0]);
            u32 pa1 = f2tf(s[kk][2]);
            u32 pa2 = f2tf(s[kk][1]);
            u32 pa3 = f2tf(s[kk][3]);
            #pragma unroll
            for (int n = 0; n < 4; n++) {
                u32 vb0 = Vs[(kk*8 + 2*c    )*36 + n*8 + g];
                u32 vb1 = Vs[(kk*8 + 2*c + 1)*36 + n*8 + g];
                mma_tf32(O[n][0], O[n][1], O[n][2], O[n][3],
                         pa0, pa1, pa2, pa3, vb0, vb1);
            }
        }
    }

    // ---- epilogue ----
    float inv0 = 1.f / l0, inv1 = 1.f / l1;
    #pragma unroll
    for (int n = 0; n < 4; n++) {
        long r0o = ((long)(b*NN + q0 + g    ))*DD + h*dH + n*8 + 2*c;
        long r1o = ((long)(b*NN + q0 + g + 8))*DD + h*dH + n*8 + 2*c;
        *(float2*)(out + r0o) = make_float2(O[n][0]*inv0, O[n][1]*inv0);
        *(float2*)(out + r1o) = make_float2(O[n][2]*inv1, O[n][3]*inv1);
    }
}

// -------------------- launch ----------------------------------------------
extern "C" void kernel_launch(void* const* d_in, const int* in_sizes, int n_in,
                              void* d_out, int out_size)
{
    const float* x      = (const float*)d_in[0];
    const float* cosb   = (const float*)d_in[1];
    const float* sinb   = (const float*)d_in[2];
    const float* w_qkv  = (const float*)d_in[3];
    const float* b_qkv  = (const float*)d_in[4];
    const float* w_proj = (const float*)d_in[5];
    const float* b_proj = (const float*)d_in[6];
    const float* ln1_g  = (const float*)d_in[7];
    const float* ln1_b  = (const float*)d_in[8];
    const float* ln2_g  = (const float*)d_in[9];
    const float* ln2_b  = (const float*)d_in[10];
    const float* w1     = (const float*)d_in[11];
    const float* b1     = (const float*)d_in[12];
    const float* w2     = (const float*)d_in[13];
    const float* b2     = (const float*)d_in[14];
    float* out = (float*)d_out;

    float *sp_h, *sp_qkv, *sp_att, *sp_x2, *sp_mid;
    cudaGetSymbolAddress((void**)&sp_h,   g_h);
    cudaGetSymbolAddress((void**)&sp_qkv, g_qkv);
    cudaGetSymbolAddress((void**)&sp_att, g_att);
    cudaGetSymbolAddress((void**)&sp_x2,  g_x2);
    cudaGetSymbolAddress((void**)&sp_mid, g_mid);

    // 1) h = LN1(x)
    ln_kernel<<<ROWS, 256>>>(x, ln1_g, ln1_b, sp_h);
    // 2) qkv = h @ w_qkv + b_qkv        [8192, 768]
    gemm_tc_kernel<<<dim3(768/128, ROWS/128), 256>>>(sp_h, w_qkv, b_qkv, nullptr,
                                                     sp_qkv, ROWS, 768, DD, 0);
    // 3) RoPE(q), RoPE(k) in place
    rope_kernel<<<(BB*NN*2*HH*16)/256, 256>>>(sp_qkv, cosb, sinb);
    // 4) attention -> att [8192, 256]  (tensor-core path)
    attn_mma_kernel<<<dim3(NN/64, BB*HH), 128>>>(sp_qkv, sp_att);
    // 5) x2 = x + att @ w_proj + b_proj
    gemm_tc_kernel<<<dim3(DD/128, ROWS/128), 256>>>(sp_att, w_proj, b_proj, x,
                                                    sp_x2, ROWS, DD, DD, 0);
    // 6) h = LN2(x2)
    ln_kernel<<<ROWS, 256>>>(sp_x2, ln2_g, ln2_b, sp_h);
    // 7) mid = relu(h @ w1 + b1)        [8192, 512]
    gemm_tc_kernel<<<dim3(512/128, ROWS/128), 256>>>(sp_h, w1, b1, nullptr,
                                                     sp_mid, ROWS, 512, DD, 1);
    // 8) out = x2 + mid @ w2 + b2
    gemm_tc_kernel<<<dim3(DD/128, ROWS/128), 256>>>(sp_mid, w2, b2, sp_x2,
                                                    out, ROWS, DD, 2*DD, 0);
}

// round 13
// speedup vs baseline: 4.1596x; 1.1650x over previous
#include <cuda_runtime.h>
#include <cuda_bf16.h>
#include <math.h>

// Shapes (fixed for this problem)
#define BB 4
#define NN 2048
#define DD 256
#define HH 8
#define dH 32
#define ROWS (BB*NN)            // 8192
#define SCALE 0.17677669529663687f   // 1/sqrt(32)

typedef unsigned long long u64;
typedef unsigned int u32;

// -------- tf32 mma.sync (operands = raw fp32 bits, HW truncates) ----------
__device__ __forceinline__ void mma_tf32(
    float& d0, float& d1, float& d2, float& d3,
    u32 a0, u32 a1, u32 a2, u32 a3, u32 b0, u32 b1)
{
    asm("mma.sync.aligned.m16n8k8.row.col.f32.tf32.tf32.f32 "
        "{%0,%1,%2,%3}, {%4,%5,%6,%7}, {%8,%9}, {%0,%1,%2,%3};"
        : "+f"(d0), "+f"(d1), "+f"(d2), "+f"(d3)
        : "r"(a0), "r"(a1), "r"(a2), "r"(a3), "r"(b0), "r"(b1));
}

// -------- cp.async helpers ------------------------------------------------
__device__ __forceinline__ void cp16(u32 smem_dst, const void* gsrc) {
    asm volatile("cp.async.cg.shared.global [%0], [%1], 16;\n"
                 :: "r"(smem_dst), "l"(gsrc));
}
__device__ __forceinline__ void cp_commit() {
    asm volatile("cp.async.commit_group;\n");
}
template <int N>
__device__ __forceinline__ void cp_wait() {
    asm volatile("cp.async.wait_group %0;\n" :: "n"(N));
}

// -------------------- scratch (device globals; no allocation allowed) -----
__device__ float g_h  [ROWS*DD];
__device__ float g_qkv[ROWS*3*DD];
__device__ float g_att[ROWS*DD];
__device__ float g_x2 [ROWS*DD];
__device__ float g_mid[ROWS*2*DD];

// -------------------- LayerNorm: one block per row ------------------------
__global__ void __launch_bounds__(256) ln_kernel(
    const float* __restrict__ x, const float* __restrict__ g,
    const float* __restrict__ b, float* __restrict__ y)
{
    int row = blockIdx.x;
    int t = threadIdx.x;
    float v = x[(long)row*DD + t];
    float s = v, s2 = v*v;
    #pragma unroll
    for (int o = 16; o; o >>= 1) {
        s  += __shfl_xor_sync(0xffffffffu, s,  o);
        s2 += __shfl_xor_sync(0xffffffffu, s2, o);
    }
    __shared__ float ws[8], ws2[8];
    int w = t >> 5, l = t & 31;
    if (l == 0) { ws[w] = s; ws2[w] = s2; }
    __syncthreads();
    s = 0.f; s2 = 0.f;
    #pragma unroll
    for (int i = 0; i < 8; i++) { s += ws[i]; s2 += ws2[i]; }
    float mu  = s * (1.f/DD);
    float var = s2 * (1.f/DD) - mu*mu;
    float inv = rsqrtf(var + 1e-5f);
    y[(long)row*DD + t] = (v - mu) * inv * g[t] + b[t];
}

// -------------------- tf32 tensor-core GEMM, cp.async double buffer -------
// C[M,Nn] = A[M,K] @ B[K,Nn] (+bias)(+relu)(+Res). 256 thr, tile 128x128,
// BK=16. Warp grid 2(M)x4(N): each warp 64x32 = 4x4 m16n8k8 tiles.
// As: swizzled [row][16] words, chunk' = chunk ^ ((row>>1)&3).
// Bs: [16][136] words (136 % 32 == 8 -> conflict-free frag reads).
#define GS 136
__global__ void __launch_bounds__(256) gemm_tc_kernel(
    const float* __restrict__ A, const float* __restrict__ B,
    const float* __restrict__ bias, const float* __restrict__ Res,
    float* __restrict__ C, int M, int Nn, int K, int relu)
{
    __shared__ u32 As[2][128*16];
    __shared__ u32 Bs[2][16*GS];

    int tid = threadIdx.x;
    int lane = tid & 31, warp = tid >> 5;
    int g = lane >> 2, c = lane & 3;
    int wm = warp & 1, wn = warp >> 1;
    int m0 = blockIdx.y * 128, n0 = blockIdx.x * 128;

    // per-thread staging coordinates (2 chunks of 16B for A, 2 for B)
    int ar[2], ac[2], br_[2], bc_[2];
    u32 adst[2], bdst[2];
    #pragma unroll
    for (int l = 0; l < 2; l++) {
        int idx = l*256 + tid;
        ar[l] = idx >> 2; ac[l] = idx & 3;
        br_[l] = idx >> 5; bc_[l] = (idx & 31) << 2;
        adst[l] = (u32)__cvta_generic_to_shared(
            &As[0][ar[l]*16 + (ac[l] ^ ((ar[l] >> 1) & 3))*4]);
        bdst[l] = (u32)__cvta_generic_to_shared(&Bs[0][br_[l]*GS + bc_[l]]);
    }
    const u32 abuf_sz = 128*16*4, bbuf_sz = 16*GS*4;

    int T = K >> 4;

    // issue tile 0
    #pragma unroll
    for (int l = 0; l < 2; l++) {
        cp16(adst[l], A + (long)(m0 + ar[l])*K + ac[l]*4);
        cp16(bdst[l], B + (long)br_[l]*Nn + n0 + bc_[l]);
    }
    cp_commit();

    float acc[4][4][4];
    #pragma unroll
    for (int mt = 0; mt < 4; mt++)
        #pragma unroll
        for (int nt = 0; nt < 4; nt++)
            #pragma unroll
            for (int i = 0; i < 4; i++) acc[mt][nt][i] = 0.f;

    int xr = (g >> 1) & 3;

    for (int t = 0; t < T; t++) {
        int buf = t & 1;
        if (t + 1 < T) {
            int nbuf = (t + 1) & 1;
            int kt = (t + 1) << 4;
            #pragma unroll
            for (int l = 0; l < 2; l++) {
                cp16(adst[l] + nbuf*abuf_sz, A + (long)(m0 + ar[l])*K + kt + ac[l]*4);
                cp16(bdst[l] + nbuf*bbuf_sz, B + (long)(kt + br_[l])*Nn + n0 + bc_[l]);
            }
            cp_commit();
            cp_wait<1>();
        } else {
            cp_wait<0>();
        }
        __syncthreads();

        const u32* Ab = As[buf];
        const u32* Bb = Bs[buf];
        #pragma unroll
        for (int kk = 0; kk < 2; kk++) {
            u32 bf[4][2];
            #pragma unroll
            for (int nt = 0; nt < 4; nt++) {
                int n = wn*32 + nt*8 + g;
                bf[nt][0] = Bb[(kk*8 + c    )*GS + n];
                bf[nt][1] = Bb[(kk*8 + c + 4)*GS + n];
            }
            int off0 = ((2*kk    ) ^ xr)*4 + c;
            int off1 = ((2*kk + 1) ^ xr)*4 + c;
            #pragma unroll
            for (int mt = 0; mt < 4; mt++) {
                int row = wm*64 + mt*16 + g;
                u32 a0 = Ab[ row     *16 + off0];
                u32 a1 = Ab[(row + 8)*16 + off0];
                u32 a2 = Ab[ row     *16 + off1];
                u32 a3 = Ab[(row + 8)*16 + off1];
                #pragma unroll
                for (int nt = 0; nt < 4; nt++)
                    mma_tf32(acc[mt][nt][0], acc[mt][nt][1],
                             acc[mt][nt][2], acc[mt][nt][3],
                             a0, a1, a2, a3, bf[nt][0], bf[nt][1]);
            }
        }
        __syncthreads();
    }

    // epilogue
    #pragma unroll
    for (int nt = 0; nt < 4; nt++) {
        int col = n0 + wn*32 + nt*8 + 2*c;
        float2 bv = *(const float2*)(bias + col);
        #pragma unroll
        for (int mt = 0; mt < 4; mt++) {
            long r0 = m0 + wm*64 + mt*16 + g;
            long r1 = r0 + 8;
            float v0 = acc[mt][nt][0] + bv.x;
            float v1 = acc[mt][nt][1] + bv.y;
            float v2 = acc[mt][nt][2] + bv.x;
            float v3 = acc[mt][nt][3] + bv.y;
            if (relu) {
                v0 = fmaxf(v0, 0.f); v1 = fmaxf(v1, 0.f);
                v2 = fmaxf(v2, 0.f); v3 = fmaxf(v3, 0.f);
            }
            if (Res) {
                float2 q0 = *(const float2*)(Res + r0*Nn + col);
                float2 q1 = *(const float2*)(Res + r1*Nn + col);
                v0 += q0.x; v1 += q0.y; v2 += q1.x; v3 += q1.y;
            }
            *(float2*)(C + r0*Nn + col) = make_float2(v0, v1);
            *(float2*)(C + r1*Nn + col) = make_float2(v2, v3);
        }
    }
}

// -------------------- RoPE in-place on q,k parts of qkv -------------------
__global__ void __launch_bounds__(256) rope_kernel(
    float* __restrict__ qkv, const float* __restrict__ cosb,
    const float* __restrict__ sinb)
{
    int gid = blockIdx.x * 256 + threadIdx.x;
    int i = gid & 15;
    int h = (gid >> 4) & 7;
    int t = (gid >> 7) & 1;
    int n = (gid >> 8) & 2047;
    int b = gid >> 19;
    float c = cosb[n*16 + i], s = sinb[n*16 + i];
    long base = ((long)(b*NN + n))*(3*DD) + t*DD + h*dH + 2*i;
    float e = qkv[base], o = qkv[base+1];
    qkv[base]   = e*c - o*s;
    qkv[base+1] = e*s + o*c;
}

// -------------------- Flash attention: tf32 mma + cp.async pipeline -------
// 256 thr (8 warps x 16 q-rows = 128 q-rows/CTA). 64-key K/V tiles double-
// buffered via cp.async. All tf32 operands are raw fp32 bits (HW truncates).
__global__ void __launch_bounds__(256) attn_mma_kernel(
    const float* __restrict__ qkv, float* __restrict__ out)
{
    int bh = blockIdx.y;                 // b*8 + h
    int b = bh >> 3, h = bh & 7;
    int warp = threadIdx.x >> 5, lane = threadIdx.x & 31;
    int g = lane >> 2, c = lane & 3;
    int q0 = blockIdx.x * 128 + warp * 16;

    __shared__ u32 Ks[2][64*36];
    __shared__ u32 Vs[2][64*36];

    const float* qb = qkv + (long)(b*NN)*(3*DD) + h*dH;       // + row*768
    const float* kb = qb + DD;
    const float* vb = qb + 2*DD;

    // per-thread staging coords: 2 iters x (K 16B + V 16B)
    int skey[2], sd4[2];
    u32 kdst[2], vdst[2];
    #pragma unroll
    for (int it = 0; it < 2; it++) {
        int i = it*256 + threadIdx.x;
        skey[it] = i >> 3; sd4[it] = (i & 7) << 2;
        kdst[it] = (u32)__cvta_generic_to_shared(&Ks[0][skey[it]*36 + sd4[it]]);
        vdst[it] = (u32)__cvta_generic_to_shared(&Vs[0][skey[it]*36 + sd4[it]]);
    }
    const u32 buf_sz = 64*36*4;

    // ---- Q fragments (scaled), raw bits ----
    u32 qa[4][4];
    #pragma unroll
    for (int kk = 0; kk < 4; kk++) {
        int col = kk*8 + c;
        qa[kk][0] = __float_as_uint(qb[(long)(q0+g  )*768 + col    ] * SCALE);
        qa[kk][1] = __float_as_uint(qb[(long)(q0+g+8)*768 + col    ] * SCALE);
        qa[kk][2] = __float_as_uint(qb[(long)(q0+g  )*768 + col + 4] * SCALE);
        qa[kk][3] = __float_as_uint(qb[(long)(q0+g+8)*768 + col + 4] * SCALE);
    }

    // issue tile 0
    #pragma unroll
    for (int it = 0; it < 2; it++) {
        long goff = (long)skey[it]*768 + sd4[it];
        cp16(kdst[it], kb + goff);
        cp16(vdst[it], vb + goff);
    }
    cp_commit();

    float O[4][4];
    #pragma unroll
    for (int n = 0; n < 4; n++)
        #pragma unroll
        for (int i = 0; i < 4; i++) O[n][i] = 0.f;
    float m0 = -1e30f, m1 = -1e30f, l0 = 0.f, l1 = 0.f;

    const int T = NN/64;
    for (int jt = 0; jt < T; jt++) {
        int buf = jt & 1;
        if (jt + 1 < T) {
            int nbuf = (jt + 1) & 1;
            #pragma unroll
            for (int it = 0; it < 2; it++) {
                long goff = (long)((jt+1)*64 + skey[it])*768 + sd4[it];
                cp16(kdst[it] + nbuf*buf_sz, kb + goff);
                cp16(vdst[it] + nbuf*buf_sz, vb + goff);
            }
            cp_commit();
            cp_wait<1>();
        } else {
            cp_wait<0>();
        }
        __syncthreads();

        const u32* Kb = Ks[buf];
        const u32* Vb = Vs[buf];

        // ---- S = Q K^T : 8 key-subtiles x 4 k-steps ----
        float s[8][4];
        #pragma unroll
        for (int n = 0; n < 8; n++) {
            s[n][0] = s[n][1] = s[n][2] = s[n][3] = 0.f;
            #pragma unroll
            for (int kk = 0; kk < 4; kk++) {
                u32 b0 = Kb[(n*8 + g)*36 + kk*8 + c    ];
                u32 b1 = Kb[(n*8 + g)*36 + kk*8 + c + 4];
                mma_tf32(s[n][0], s[n][1], s[n][2], s[n][3],
                         qa[kk][0], qa[kk][1], qa[kk][2], qa[kk][3], b0, b1);
            }
        }

        // ---- online softmax (rows g and g+8) ----
        float t0 = -1e30f, t1 = -1e30f;
        #pragma unroll
        for (int n = 0; n < 8; n++) {
            t0 = fmaxf(t0, fmaxf(s[n][0], s[n][1]));
            t1 = fmaxf(t1, fmaxf(s[n][2], s[n][3]));
        }
        #pragma unroll
        for (int o = 1; o <= 2; o <<= 1) {
            t0 = fmaxf(t0, __shfl_xor_sync(0xffffffffu, t0, o));
            t1 = fmaxf(t1, __shfl_xor_sync(0xffffffffu, t1, o));
        }
        float nm0 = fmaxf(m0, t0), nm1 = fmaxf(m1, t1);
        float cor0 = __expf(m0 - nm0), cor1 = __expf(m1 - nm1);
        l0 *= cor0; l1 *= cor1;
        #pragma unroll
        for (int n = 0; n < 4; n++) {
            O[n][0] *= cor0; O[n][1] *= cor0;
            O[n][2] *= cor1; O[n][3] *= cor1;
        }
        float rs0 = 0.f, rs1 = 0.f;
        #pragma unroll
        for (int n = 0; n < 8; n++) {
            s[n][0] = __expf(s[n][0] - nm0);
            s[n][1] = __expf(s[n][1] - nm0);
            s[n][2] = __expf(s[n][2] - nm1);
            s[n][3] = __expf(s[n][3] - nm1);
            rs0 += s[n][0] + s[n][1];
            rs1 += s[n][2] + s[n][3];
        }
        #pragma unroll
        for (int o = 1; o <= 2; o <<= 1) {
            rs0 += __shfl_xor_sync(0xffffffffu, rs0, o);
            rs1 += __shfl_xor_sync(0xffffffffu, rs1, o);
        }
        l0 += rs0; l1 += rs1;
        m0 = nm0; m1 = nm1;

        // ---- O += P V : P C-frags reused as A-frags; V rows permuted ----
        #pragma unroll
        for (int kk = 0; kk < 8; kk++) {
            u32 pa0 = __float_as_uint(s[kk][0]);
            u32 pa1 = __float_as_uint(s[kk][2]);
            u32 pa2 = __float_as_uint(s[kk][1]);
            u32 pa3 = __float_as_uint(s[kk][3]);
            #pragma unroll
            for (int n = 0; n < 4; n++) {
                u32 vb0 = Vb[(kk*8 + 2*c    )*36 + n*8 + g];
                u32 vb1 = Vb[(kk*8 + 2*c + 1)*36 + n*8 + g];
                mma_tf32(O[n][0], O[n][1], O[n][2], O[n][3],
                         pa0, pa1, pa2, pa3, vb0, vb1);
            }
        }
        __syncthreads();
    }

    // ---- epilogue ----
    float inv0 = 1.f / l0, inv1 = 1.f / l1;
    #pragma unroll
    for (int n = 0; n < 4; n++) {
        long r0o = ((long)(b*NN + q0 + g    ))*DD + h*dH + n*8 + 2*c;
        long r1o = ((long)(b*NN + q0 + g + 8))*DD + h*dH + n*8 + 2*c;
        *(float2*)(out + r0o) = make_float2(O[n][0]*inv0, O[n][1]*inv0);
        *(float2*)(out + r1o) = make_float2(O[n][2]*inv1, O[n][3]*inv1);
    }
}

// -------------------- launch ----------------------------------------------
extern "C" void kernel_launch(void* const* d_in, const int* in_sizes, int n_in,
                              void* d_out, int out_size)
{
    const float* x      = (const float*)d_in[0];
    const float* cosb   = (const float*)d_in[1];
    const float* sinb   = (const float*)d_in[2];
    const float* w_qkv  = (const float*)d_in[3];
    const float* b_qkv  = (const float*)d_in[4];
    const float* w_proj = (const float*)d_in[5];
    const float* b_proj = (const float*)d_in[6];
    const float* ln1_g  = (const float*)d_in[7];
    const float* ln1_b  = (const float*)d_in[8];
    const float* ln2_g  = (const float*)d_in[9];
    const float* ln2_b  = (const float*)d_in[10];
    const float* w1     = (const float*)d_in[11];
    const float* b1     = (const float*)d_in[12];
    const float* w2     = (const float*)d_in[13];
    const float* b2     = (const float*)d_in[14];
    float* out = (float*)d_out;

    float *sp_h, *sp_qkv, *sp_att, *sp_x2, *sp_mid;
    cudaGetSymbolAddress((void**)&sp_h,   g_h);
    cudaGetSymbolAddress((void**)&sp_qkv, g_qkv);
    cudaGetSymbolAddress((void**)&sp_att, g_att);
    cudaGetSymbolAddress((void**)&sp_x2,  g_x2);
    cudaGetSymbolAddress((void**)&sp_mid, g_mid);

    // 1) h = LN1(x)
    ln_kernel<<<ROWS, 256>>>(x, ln1_g, ln1_b, sp_h);
    // 2) qkv = h @ w_qkv + b_qkv        [8192, 768]
    gemm_tc_kernel<<<dim3(768/128, ROWS/128), 256>>>(sp_h, w_qkv, b_qkv, nullptr,
                                                     sp_qkv, ROWS, 768, DD, 0);
    // 3) RoPE(q), RoPE(k) in place
    rope_kernel<<<(BB*NN*2*HH*16)/256, 256>>>(sp_qkv, cosb, sinb);
    // 4) attention -> att [8192, 256]  (tensor-core path)
    attn_mma_kernel<<<dim3(NN/128, BB*HH), 256>>>(sp_qkv, sp_att);
    // 5) x2 = x + att @ w_proj + b_proj
    gemm_tc_kernel<<<dim3(DD/128, ROWS/128), 256>>>(sp_att, w_proj, b_proj, x,
                                                    sp_x2, ROWS, DD, DD, 0);
    // 6) h = LN2(x2)
    ln_kernel<<<ROWS, 256>>>(sp_x2, ln2_g, ln2_b, sp_h);
    // 7) mid = relu(h @ w1 + b1)        [8192, 512]
    gemm_tc_kernel<<<dim3(512/128, ROWS/128), 256>>>(sp_h, w1, b1, nullptr,
                                                     sp_mid, ROWS, 512, DD, 1);
    // 8) out = x2 + mid @ w2 + b2
    gemm_tc_kernel<<<dim3(DD/128, ROWS/128), 256>>>(sp_mid, w2, b2, sp_x2,
                                                    out, ROWS, DD, 2*DD, 0);
}